// round 12
// baseline (speedup 1.0000x reference)
#include <cuda_runtime.h>

#define BATCH  32
#define NP     4096
#define NSLOT  64                // slot = w*32 + b; opposite cloud = s ^ 32
#define NBX    64
#define NBY    64
#define NB2    (NBX * NBY)
#define XMIN   (-5.0f)
#define W      0.15625f          // 10/64, exact in fp32
#define INVW   6.4f

// candidates binned by (x,y), y-minor; preprocessed: (-2x, -2y, -2z, ||c||^2)
__device__ float4         g_pts[NSLOT][NP];
__device__ unsigned short g_qid[NSLOT][NP];
__device__ int            g_bs[NSLOT][NB2 + 1];
__device__ float          g_dist[NSLOT][NP];   // by ORIGINAL index
__device__ int            g_ovn[NSLOT];        // overflow counts
__device__ unsigned short g_ovq[NSLOT][NP];    // overflow sorted-ranks
__device__ float          g_ovm[NSLOT][NP];    // overflow pass-1 m

static __device__ __forceinline__ int bco(float v) {
    int b = (int)floorf((v - XMIN) * INVW);
    return min(max(b, 0), NBX - 1);
}

// ---------------------------------------------------------------------------
// 1) per-slot counting sort by (x,y)-bin (+ preprocess). One block per slot.
// ---------------------------------------------------------------------------
__global__ void __launch_bounds__(512)
prep_kernel(const float* __restrict__ x1, const float* __restrict__ x2) {
    __shared__ int hist[NB2];
    __shared__ int cur[NB2];
    __shared__ int wsum[16];

    const int s = blockIdx.x;
    const int w = s >> 5, b = s & 31;
    const float* src = (w ? x2 : x1) + (size_t)b * NP * 3;
    const int tid = threadIdx.x;

    if (tid == 0) g_ovn[s] = 0;
    for (int i = tid; i < NB2; i += 512) hist[i] = 0;
    __syncthreads();

    for (int i = tid; i < NP; i += 512) {
        int bn = bco(src[3 * i]) * NBY + bco(src[3 * i + 1]);
        atomicAdd(&hist[bn], 1);
    }
    __syncthreads();

    const int per = NB2 / 512;
    const int base = tid * per;
    int lsum = 0;
    #pragma unroll
    for (int i = 0; i < per; i++) lsum += hist[base + i];

    int lane = tid & 31, wid = tid >> 5;
    int v = lsum;
    #pragma unroll
    for (int o = 1; o < 32; o <<= 1) {
        int n = __shfl_up_sync(0xffffffffu, v, o);
        if (lane >= o) v += n;
    }
    if (lane == 31) wsum[wid] = v;
    __syncthreads();
    if (wid == 0) {
        int t = (lane < 16) ? wsum[lane] : 0;
        #pragma unroll
        for (int o = 1; o < 16; o <<= 1) {
            int n = __shfl_up_sync(0xffffffffu, t, o);
            if (lane >= o) t += n;
        }
        if (lane < 16) wsum[lane] = t;
    }
    __syncthreads();
    int run = (v - lsum) + (wid > 0 ? wsum[wid - 1] : 0);

    #pragma unroll
    for (int i = 0; i < per; i++) {
        int c = hist[base + i];
        g_bs[s][base + i] = run;
        cur[base + i] = run;
        run += c;
    }
    if (tid == 0) g_bs[s][NB2] = NP;
    __syncthreads();

    for (int i = tid; i < NP; i += 512) {
        float x = src[3 * i], y = src[3 * i + 1], z = src[3 * i + 2];
        int bn = bco(x) * NBY + bco(y);
        int pos = atomicAdd(&cur[bn], 1);
        g_pts[s][pos] = make_float4(-2.0f * x, -2.0f * y, -2.0f * z,
                                    x * x + y * y + z * z);
        g_qid[s][pos] = (unsigned short)i;
    }
}

#define SCAN4(S, E)                                                             \
    {                                                                           \
        int _i = (S), _e = (E);                                                 \
        for (; _i + 4 <= _e; _i += 4) {                                         \
            float4 c0 = ptsc[_i],     c1 = ptsc[_i + 1];                        \
            float4 c2 = ptsc[_i + 2], c3 = ptsc[_i + 3];                        \
            m0 = fminf(m0, fmaf(qx, c0.x, fmaf(qy, c0.y, fmaf(qz, c0.z, c0.w)))); \
            m1 = fminf(m1, fmaf(qx, c1.x, fmaf(qy, c1.y, fmaf(qz, c1.z, c1.w)))); \
            m2 = fminf(m2, fmaf(qx, c2.x, fmaf(qy, c2.y, fmaf(qz, c2.z, c2.w)))); \
            m3 = fminf(m3, fmaf(qx, c3.x, fmaf(qy, c3.y, fmaf(qz, c3.z, c3.w)))); \
        }                                                                       \
        for (; _i < _e; _i++) {                                                 \
            float4 c0 = ptsc[_i];                                               \
            m0 = fminf(m0, fmaf(qx, c0.x, fmaf(qy, c0.y, fmaf(qz, c0.z, c0.w)))); \
        }                                                                       \
    }

// ---------------------------------------------------------------------------
// 2) pass 1: one fixed warp-uniform rect scan + single bound check.
// ---------------------------------------------------------------------------
__global__ void __launch_bounds__(256)
pass1_kernel() {
    const unsigned FULL = 0xffffffffu;
    const int sq = blockIdx.y;
    const int sc = sq ^ 32;
    const int qi = blockIdx.x * 256 + threadIdx.x;

    const float4* __restrict__ ptsq = g_pts[sq];
    const float4* __restrict__ ptsc = g_pts[sc];
    const int*    __restrict__ bs   = g_bs[sc];

    float4 qp = ptsq[qi];
    const int qid = g_qid[sq][qi];
    const float qx = -0.5f * qp.x;
    const float qy = -0.5f * qp.y;
    const float qz = -0.5f * qp.z;
    const float qq = qp.w;

    const int bx = bco(qx);
    const int by = bco(qy);
    const int xlo = max(__reduce_min_sync(FULL, bx) - 1, 0);
    const int xhi = min(__reduce_max_sync(FULL, bx) + 1, NBX - 1);
    const int ylo = max(__reduce_min_sync(FULL, by) - 1, 0);
    const int yhi = min(__reduce_max_sync(FULL, by) + 1, NBY - 1);

    const float INF = __int_as_float(0x7f800000);
    float m0 = INF, m1 = INF, m2 = INF, m3 = INF;

    for (int x = xlo; x <= xhi; x++)
        SCAN4(bs[x * NBY + ylo], bs[x * NBY + yhi + 1]);

    float m = fminf(fminf(m0, m1), fminf(m2, m3));
    float el = (xlo == 0)       ? INF : qx - (XMIN + (float)xlo * W);
    float eh = (xhi == NBX - 1) ? INF : (XMIN + (float)(xhi + 1) * W) - qx;
    float fl = (ylo == 0)       ? INF : qy - (XMIN + (float)ylo * W);
    float fh = (yhi == NBY - 1) ? INF : (XMIN + (float)(yhi + 1) * W) - qy;
    float bnd = fminf(fminf(el, eh), fminf(fl, fh));
    float best = qq + m;

    if (best <= bnd * bnd * 0.9999f) {
        g_dist[sq][qid] = best;
    } else {
        int k = atomicAdd(&g_ovn[sq], 1);
        g_ovq[sq][k] = (unsigned short)qi;
        g_ovm[sq][k] = m;
    }
}

// ---------------------------------------------------------------------------
// 3) pass 2: overflow queries. Radius known from pass 1 -> one exact rect
//    (warp-union), scanned once with broadcast loads. Order-independent.
// ---------------------------------------------------------------------------
__global__ void __launch_bounds__(256)
pass2_kernel() {
    const unsigned FULL = 0xffffffffu;
    const int sq = blockIdx.y;
    const int sc = sq ^ 32;
    const int n  = g_ovn[sq];
    const int base = blockIdx.x * 256;
    if (base >= n) return;                      // block-uniform exit

    const float4* __restrict__ ptsq = g_pts[sq];
    const float4* __restrict__ ptsc = g_pts[sc];
    const int*    __restrict__ bs   = g_bs[sc];

    const int idx = min(base + threadIdx.x, n - 1);   // clamp: duplicates OK
    const int qi  = g_ovq[sq][idx];
    const float mp = g_ovm[sq][idx];

    float4 qp = ptsq[qi];
    const int qid = g_qid[sq][qi];
    const float qx = -0.5f * qp.x;
    const float qy = -0.5f * qp.y;
    const float qz = -0.5f * qp.z;
    const float qq = qp.w;

    // ball radius that provably contains the true NN
    float d2 = (qq + mp) * 1.0002f + 1e-6f;
    float d  = sqrtf(d2);

    int xl = bco(qx - d), xh = bco(qx + d);
    int yl = bco(qy - d), yh = bco(qy + d);
    const int xlo = __reduce_min_sync(FULL, xl);
    const int xhi = __reduce_max_sync(FULL, xh);
    const int ylo = __reduce_min_sync(FULL, yl);
    const int yhi = __reduce_max_sync(FULL, yh);

    const float INF = __int_as_float(0x7f800000);
    float m0 = INF, m1 = INF, m2 = INF, m3 = INF;

    for (int x = xlo; x <= xhi; x++)
        SCAN4(bs[x * NBY + ylo], bs[x * NBY + yhi + 1]);

    float m = fminf(fminf(fminf(m0, m1), fminf(m2, m3)), mp);
    g_dist[sq][qid] = qq + m;
}

// ---------------------------------------------------------------------------
// 4) deterministic fixed-order reduce
// ---------------------------------------------------------------------------
__global__ void __launch_bounds__(256)
reduce_kernel(float* __restrict__ out) {
    const int b = blockIdx.x, tid = threadIdx.x;
    float s = 0.0f;
    #pragma unroll
    for (int d = 0; d < 2; d++)
        for (int i = tid; i < NP; i += 256)
            s += g_dist[d * BATCH + b][i];

    __shared__ float red[256];
    red[tid] = s;
    __syncthreads();
    #pragma unroll
    for (int o = 128; o > 0; o >>= 1) {
        if (tid < o) red[tid] += red[tid + o];
        __syncthreads();
    }
    if (tid == 0) out[b] = red[0] * (1.0f / (float)NP);
}

extern "C" void kernel_launch(void* const* d_in, const int* in_sizes, int n_in,
                              void* d_out, int out_size) {
    const float* x1 = (const float*)d_in[0];
    const float* x2 = (const float*)d_in[1];
    float* out = (float*)d_out;

    prep_kernel<<<NSLOT, 512>>>(x1, x2);
    pass1_kernel<<<dim3(NP / 256, NSLOT), 256>>>();
    pass2_kernel<<<dim3(NP / 256, NSLOT), 256>>>();
    reduce_kernel<<<BATCH, 256>>>(out);
}

// round 13
// speedup vs baseline: 1.5235x; 1.5235x over previous
#include <cuda_runtime.h>

#define BATCH  32
#define NP     4096
#define NSLOT  64                // slot = w*32 + b; opposite cloud = s ^ 32
#define NB     128               // x-bins
#define XMIN   (-5.0f)
#define W      0.078125f         // 10/128, exact in fp32
#define INVW   12.8f

// candidates binned by x; preprocessed: (-2x, -2y, -2z, ||c||^2)
__device__ float4         g_pts[NSLOT][NP];
__device__ unsigned short g_qid[NSLOT][NP];
__device__ int            g_bs[NSLOT][NB + 1];
__device__ float          g_dist[NSLOT][NP];   // by ORIGINAL index

static __device__ __forceinline__ int bco(float v) {
    int b = (int)floorf((v - XMIN) * INVW);
    return min(max(b, 0), NB - 1);
}

// ---------------------------------------------------------------------------
// 1) per-slot counting sort by x-bin (+ preprocess). One block per slot.
// ---------------------------------------------------------------------------
__global__ void __launch_bounds__(512)
prep_kernel(const float* __restrict__ x1, const float* __restrict__ x2) {
    __shared__ int hist[NB];
    __shared__ int cur[NB];

    const int s = blockIdx.x;
    const int w = s >> 5, b = s & 31;
    const float* src = (w ? x2 : x1) + (size_t)b * NP * 3;
    const int tid = threadIdx.x;

    if (tid < NB) hist[tid] = 0;
    __syncthreads();

    for (int i = tid; i < NP; i += 512)
        atomicAdd(&hist[bco(src[3 * i])], 1);
    __syncthreads();

    // warp 0: exclusive scan of 128 bins (4 bins per lane)
    if (tid < 32) {
        int base = tid * 4;
        int h0 = hist[base], h1 = hist[base + 1];
        int h2 = hist[base + 2], h3 = hist[base + 3];
        int lsum = h0 + h1 + h2 + h3;
        int v = lsum;
        #pragma unroll
        for (int o = 1; o < 32; o <<= 1) {
            int n = __shfl_up_sync(0xffffffffu, v, o);
            if (tid >= o) v += n;
        }
        int run = v - lsum;                    // exclusive prefix
        g_bs[s][base] = run;     cur[base] = run;     run += h0;
        g_bs[s][base + 1] = run; cur[base + 1] = run; run += h1;
        g_bs[s][base + 2] = run; cur[base + 2] = run; run += h2;
        g_bs[s][base + 3] = run; cur[base + 3] = run;
        if (tid == 31) g_bs[s][NB] = NP;
    }
    __syncthreads();

    for (int i = tid; i < NP; i += 512) {
        float x = src[3 * i], y = src[3 * i + 1], z = src[3 * i + 2];
        int pos = atomicAdd(&cur[bco(x)], 1);
        g_pts[s][pos] = make_float4(-2.0f * x, -2.0f * y, -2.0f * z,
                                    x * x + y * y + z * z);
        g_qid[s][pos] = (unsigned short)i;
    }
}

// scan [S,E) of the SMEM-staged candidates with 4 accumulators
#define SCAN_SM(S, E)                                                           \
    {                                                                           \
        int _i = (S), _e = (E);                                                 \
        for (; _i + 4 <= _e; _i += 4) {                                         \
            float4 c0 = scand[_i],     c1 = scand[_i + 1];                      \
            float4 c2 = scand[_i + 2], c3 = scand[_i + 3];                      \
            m0 = fminf(m0, fmaf(qx, c0.x, fmaf(qy, c0.y, fmaf(qz, c0.z, c0.w)))); \
            m1 = fminf(m1, fmaf(qx, c1.x, fmaf(qy, c1.y, fmaf(qz, c1.z, c1.w)))); \
            m2 = fminf(m2, fmaf(qx, c2.x, fmaf(qy, c2.y, fmaf(qz, c2.z, c2.w)))); \
            m3 = fminf(m3, fmaf(qx, c3.x, fmaf(qy, c3.y, fmaf(qz, c3.z, c3.w)))); \
        }                                                                       \
        for (; _i < _e; _i++) {                                                 \
            float4 c0 = scand[_i];                                              \
            m0 = fminf(m0, fmaf(qx, c0.x, fmaf(qy, c0.y, fmaf(qz, c0.z, c0.w)))); \
        }                                                                       \
    }

// ---------------------------------------------------------------------------
// 2) query kernel: whole candidate cloud staged in dynamic SMEM (64 KB).
//    Pass A: warp-uniform +/-3-bin window (broadcast LDS).
//    Pass B: block-compacted failures vs the full SMEM cloud (exact).
// ---------------------------------------------------------------------------
__global__ void __launch_bounds__(256)
query_kernel() {
    extern __shared__ float4 scand[];            // NP float4 = 64 KB
    __shared__ unsigned short flist[256];
    __shared__ int fcnt;

    const unsigned FULL = 0xffffffffu;
    const int sq = blockIdx.y;
    const int sc = sq ^ 32;                      // opposite cloud, same batch
    const int tid = threadIdx.x;
    const int qi = blockIdx.x * 256 + tid;       // bin-sorted query rank

    const float4* __restrict__ ptsq = g_pts[sq];
    const float4* __restrict__ ptsc = g_pts[sc];
    const int*    __restrict__ bs   = g_bs[sc];

    for (int j = tid; j < NP; j += 256)          // coalesced stage
        scand[j] = ptsc[j];
    if (tid == 0) fcnt = 0;
    __syncthreads();

    float4 qp = ptsq[qi];
    const int qid = g_qid[sq][qi];
    const float qx = -0.5f * qp.x;               // exact inverse of -2x
    const float qy = -0.5f * qp.y;
    const float qz = -0.5f * qp.z;
    const float qq = qp.w;

    const int qb = bco(qx);
    const int L = max(__reduce_min_sync(FULL, qb) - 3, 0);
    const int R = min(__reduce_max_sync(FULL, qb) + 3, NB - 1);
    const int s0 = bs[L], e0 = bs[R + 1];        // warp-uniform (broadcast LDG)

    const float INF = __int_as_float(0x7f800000);
    float m0 = INF, m1 = INF, m2 = INF, m3 = INF;

    SCAN_SM(s0, e0);

    float m = fminf(fminf(m0, m1), fminf(m2, m3));
    float el = (L == 0)      ? INF : qx - (XMIN + (float)L * W);
    float eh = (R == NB - 1) ? INF : (XMIN + (float)(R + 1) * W) - qx;
    float bnd = fminf(el, eh);
    float best = qq + m;

    if (best <= bnd * bnd * 0.9999f) {
        g_dist[sq][qid] = best;
    } else {
        int k = atomicAdd(&fcnt, 1);
        flist[k] = (unsigned short)qi;
    }
    __syncthreads();

    // Pass B: compacted failures scan the FULL staged cloud (exact, lockstep).
    const int cnt = fcnt;
    const int wid = tid >> 5, lane = tid & 31;
    for (int k0 = wid * 32; k0 < cnt; k0 += 256) {
        int idx = k0 + lane;
        bool act = idx < cnt;
        int fq = flist[act ? idx : 0];
        float4 fp = ptsq[fq];
        const float fqx = -0.5f * fp.x;
        const float fqy = -0.5f * fp.y;
        const float fqz = -0.5f * fp.z;
        float a0 = INF, a1 = INF, a2 = INF, a3 = INF;
        #pragma unroll 1
        for (int j = 0; j < NP; j += 4) {
            float4 c0 = scand[j],     c1 = scand[j + 1];
            float4 c2 = scand[j + 2], c3 = scand[j + 3];
            a0 = fminf(a0, fmaf(fqx, c0.x, fmaf(fqy, c0.y, fmaf(fqz, c0.z, c0.w))));
            a1 = fminf(a1, fmaf(fqx, c1.x, fmaf(fqy, c1.y, fmaf(fqz, c1.z, c1.w))));
            a2 = fminf(a2, fmaf(fqx, c2.x, fmaf(fqy, c2.y, fmaf(fqz, c2.z, c2.w))));
            a3 = fminf(a3, fmaf(fqx, c3.x, fmaf(fqy, c3.y, fmaf(fqz, c3.z, c3.w))));
        }
        if (act) {
            float fm = fminf(fminf(a0, a1), fminf(a2, a3));
            g_dist[sq][g_qid[sq][fq]] = fp.w + fm;
        }
    }
}

// ---------------------------------------------------------------------------
// 3) deterministic fixed-order reduce: out[b] = (sum_d0 + sum_d1) / NP
// ---------------------------------------------------------------------------
__global__ void __launch_bounds__(256)
reduce_kernel(float* __restrict__ out) {
    const int b = blockIdx.x, tid = threadIdx.x;
    float s = 0.0f;
    #pragma unroll
    for (int d = 0; d < 2; d++)
        for (int i = tid; i < NP; i += 256)
            s += g_dist[d * BATCH + b][i];

    __shared__ float red[256];
    red[tid] = s;
    __syncthreads();
    #pragma unroll
    for (int o = 128; o > 0; o >>= 1) {
        if (tid < o) red[tid] += red[tid + o];
        __syncthreads();
    }
    if (tid == 0) out[b] = red[0] * (1.0f / (float)NP);
}

extern "C" void kernel_launch(void* const* d_in, const int* in_sizes, int n_in,
                              void* d_out, int out_size) {
    const float* x1 = (const float*)d_in[0];
    const float* x2 = (const float*)d_in[1];
    float* out = (float*)d_out;

    cudaFuncSetAttribute(query_kernel,
                         cudaFuncAttributeMaxDynamicSharedMemorySize,
                         NP * (int)sizeof(float4));

    prep_kernel<<<NSLOT, 512>>>(x1, x2);
    query_kernel<<<dim3(NP / 256, NSLOT), 256, NP * sizeof(float4)>>>();
    reduce_kernel<<<BATCH, 256>>>(out);
}

// round 14
// speedup vs baseline: 2.6491x; 1.7389x over previous
#include <cuda_runtime.h>

#define BATCH  32
#define NP     4096
#define NSLOT  64                // slot = w*32 + b; opposite cloud = s ^ 32
#define NB     128               // x-bins
#define XMIN   (-5.0f)
#define W      0.078125f         // 10/128, exact in fp32
#define INVW   12.8f

// candidates binned by x; preprocessed: (-2x, -2y, -2z, ||c||^2)
__device__ float4         g_pts[NSLOT][NP];
__device__ unsigned short g_qid[NSLOT][NP];
__device__ int            g_bs[NSLOT][NB + 1];
__device__ float          g_dist[NSLOT][NP];   // by ORIGINAL index

static __device__ __forceinline__ int bco(float v) {
    int b = (int)floorf((v - XMIN) * INVW);
    return min(max(b, 0), NB - 1);
}

// ---------------------------------------------------------------------------
// 1) per-slot counting sort by x-bin (+ preprocess). One block per slot.
//    Raw cloud staged once into dynamic SMEM via coalesced float4 loads.
// ---------------------------------------------------------------------------
__global__ void __launch_bounds__(512)
prep_kernel(const float* __restrict__ x1, const float* __restrict__ x2) {
    extern __shared__ float sp[];               // 3*NP floats = 48 KB
    __shared__ int hist[NB];
    __shared__ int cur[NB];

    const int s = blockIdx.x;
    const int w = s >> 5, b = s & 31;
    const float* src = (w ? x2 : x1) + (size_t)b * NP * 3;
    const int tid = threadIdx.x;

    const float4* src4 = (const float4*)src;
    float4* sp4 = (float4*)sp;
    #pragma unroll
    for (int i = tid; i < 3 * NP / 4; i += 512)
        sp4[i] = src4[i];
    if (tid < NB) hist[tid] = 0;
    __syncthreads();

    for (int i = tid; i < NP; i += 512)
        atomicAdd(&hist[bco(sp[3 * i])], 1);
    __syncthreads();

    if (tid < 32) {                              // warp 0: scan 128 bins
        int base = tid * 4;
        int h0 = hist[base], h1 = hist[base + 1];
        int h2 = hist[base + 2], h3 = hist[base + 3];
        int lsum = h0 + h1 + h2 + h3;
        int v = lsum;
        #pragma unroll
        for (int o = 1; o < 32; o <<= 1) {
            int n = __shfl_up_sync(0xffffffffu, v, o);
            if (tid >= o) v += n;
        }
        int run = v - lsum;
        g_bs[s][base] = run;     cur[base] = run;     run += h0;
        g_bs[s][base + 1] = run; cur[base + 1] = run; run += h1;
        g_bs[s][base + 2] = run; cur[base + 2] = run; run += h2;
        g_bs[s][base + 3] = run; cur[base + 3] = run;
        if (tid == 31) g_bs[s][NB] = NP;
    }
    __syncthreads();

    for (int i = tid; i < NP; i += 512) {
        float x = sp[3 * i], y = sp[3 * i + 1], z = sp[3 * i + 2];
        int pos = atomicAdd(&cur[bco(x)], 1);
        g_pts[s][pos] = make_float4(-2.0f * x, -2.0f * y, -2.0f * z,
                                    x * x + y * y + z * z);
        g_qid[s][pos] = (unsigned short)i;
    }
}

// scan [S,E) of SMEM-staged candidates with 4 accumulators
#define SCAN_SM(S, E)                                                           \
    {                                                                           \
        int _i = (S), _e = (E);                                                 \
        for (; _i + 4 <= _e; _i += 4) {                                         \
            float4 c0 = scand[_i],     c1 = scand[_i + 1];                      \
            float4 c2 = scand[_i + 2], c3 = scand[_i + 3];                      \
            m0 = fminf(m0, fmaf(qx, c0.x, fmaf(qy, c0.y, fmaf(qz, c0.z, c0.w)))); \
            m1 = fminf(m1, fmaf(qx, c1.x, fmaf(qy, c1.y, fmaf(qz, c1.z, c1.w)))); \
            m2 = fminf(m2, fmaf(qx, c2.x, fmaf(qy, c2.y, fmaf(qz, c2.z, c2.w)))); \
            m3 = fminf(m3, fmaf(qx, c3.x, fmaf(qy, c3.y, fmaf(qz, c3.z, c3.w)))); \
        }                                                                       \
        for (; _i < _e; _i++) {                                                 \
            float4 c0 = scand[_i];                                              \
            m0 = fminf(m0, fmaf(qx, c0.x, fmaf(qy, c0.y, fmaf(qz, c0.z, c0.w)))); \
        }                                                                       \
    }

// ---------------------------------------------------------------------------
// 2) query kernel: cloud staged in 64 KB dynamic SMEM.
//    Pass A: warp-uniform +/-2-bin window.  Fallback: warp-union window from
//    the proven radius d = sqrt(qq+m), scanned inline from SMEM (no tails).
// ---------------------------------------------------------------------------
__global__ void __launch_bounds__(256)
query_kernel() {
    extern __shared__ float4 scand[];            // NP float4 = 64 KB

    const unsigned FULL = 0xffffffffu;
    const int sq = blockIdx.y;
    const int sc = sq ^ 32;                      // opposite cloud, same batch
    const int tid = threadIdx.x;
    const int qi = blockIdx.x * 256 + tid;       // bin-sorted query rank

    const float4* __restrict__ ptsq = g_pts[sq];
    const float4* __restrict__ ptsc = g_pts[sc];
    const int*    __restrict__ bs   = g_bs[sc];

    for (int j = tid; j < NP; j += 256)          // coalesced stage
        scand[j] = ptsc[j];
    __syncthreads();

    float4 qp = ptsq[qi];
    const int qid = g_qid[sq][qi];
    const float qx = -0.5f * qp.x;               // exact inverse of -2x
    const float qy = -0.5f * qp.y;
    const float qz = -0.5f * qp.z;
    const float qq = qp.w;

    const int qb = bco(qx);
    const int L = max(__reduce_min_sync(FULL, qb) - 2, 0);
    const int R = min(__reduce_max_sync(FULL, qb) + 2, NB - 1);
    const int s0 = bs[L], e0 = bs[R + 1];        // warp-uniform

    const float INF = __int_as_float(0x7f800000);
    float m0 = INF, m1 = INF, m2 = INF, m3 = INF;

    SCAN_SM(s0, e0);

    float m = fminf(fminf(m0, m1), fminf(m2, m3));
    float el = (L == 0)      ? INF : qx - (XMIN + (float)L * W);
    float eh = (R == NB - 1) ? INF : (XMIN + (float)(R + 1) * W) - qx;
    float bnd = fminf(el, eh);
    float best = qq + m;
    bool fail = !(best <= bnd * bnd * 0.9999f);

    if (__any_sync(FULL, fail)) {
        // proven radius: a candidate exists at distance sqrt(best)
        float d = fail ? sqrtf(best * 1.0002f + 1e-6f) : 0.0f;
        int xl = fail ? bco(qx - d) : NB - 1;    // neutral sentinels
        int xh = fail ? bco(qx + d) : 0;
        const int FL = __reduce_min_sync(FULL, xl);
        const int FH = __reduce_max_sync(FULL, xh);
        // scan only parts outside [L,R]; m carries the inside part
        if (FL < L) SCAN_SM(bs[FL], bs[L]);
        if (FH > R) SCAN_SM(bs[R + 1], bs[FH + 1]);
        m = fminf(fminf(m0, m1), fminf(m2, m3));
        best = qq + m;
    }

    g_dist[sq][qid] = best;
}

// ---------------------------------------------------------------------------
// 3) deterministic fixed-order reduce: out[b] = (sum_d0 + sum_d1) / NP
// ---------------------------------------------------------------------------
__global__ void __launch_bounds__(256)
reduce_kernel(float* __restrict__ out) {
    const int b = blockIdx.x, tid = threadIdx.x;
    float s = 0.0f;
    #pragma unroll
    for (int d = 0; d < 2; d++)
        for (int i = tid; i < NP; i += 256)
            s += g_dist[d * BATCH + b][i];

    __shared__ float red[256];
    red[tid] = s;
    __syncthreads();
    #pragma unroll
    for (int o = 128; o > 0; o >>= 1) {
        if (tid < o) red[tid] += red[tid + o];
        __syncthreads();
    }
    if (tid == 0) out[b] = red[0] * (1.0f / (float)NP);
}

extern "C" void kernel_launch(void* const* d_in, const int* in_sizes, int n_in,
                              void* d_out, int out_size) {
    const float* x1 = (const float*)d_in[0];
    const float* x2 = (const float*)d_in[1];
    float* out = (float*)d_out;

    cudaFuncSetAttribute(prep_kernel,
                         cudaFuncAttributeMaxDynamicSharedMemorySize,
                         3 * NP * (int)sizeof(float));
    cudaFuncSetAttribute(query_kernel,
                         cudaFuncAttributeMaxDynamicSharedMemorySize,
                         NP * (int)sizeof(float4));

    prep_kernel<<<NSLOT, 512, 3 * NP * sizeof(float)>>>(x1, x2);
    query_kernel<<<dim3(NP / 256, NSLOT), 256, NP * sizeof(float4)>>>();
    reduce_kernel<<<BATCH, 256>>>(out);
}

// round 15
// speedup vs baseline: 3.0105x; 1.1364x over previous
#include <cuda_runtime.h>

#define BATCH  32
#define NP     4096
#define NSLOT  64                // slot = w*32 + b; opposite cloud = s ^ 32
#define NBX    64
#define NBY    64
#define NB2    (NBX * NBY)
#define XMIN   (-5.0f)
#define W      0.15625f          // 10/64, exact in fp32
#define INVW   6.4f

// candidates binned by (x,y), y-minor; preprocessed: (-2x, -2y, -2z, ||c||^2)
__device__ float4         g_pts[NSLOT][NP];
__device__ unsigned short g_qid[NSLOT][NP];
__device__ int            g_bs[NSLOT][NB2 + 1];
__device__ float          g_dist[NSLOT][NP];   // by ORIGINAL index

static __device__ __forceinline__ int bco(float v) {
    int b = (int)floorf((v - XMIN) * INVW);
    return min(max(b, 0), NBX - 1);
}

// ---------------------------------------------------------------------------
// 1) per-slot counting sort by (x,y)-bin. Raw cloud staged once in SMEM.
//    Dynamic smem: sp[3*NP] floats | hist[NB2] | cur[NB2]  (80 KB)
// ---------------------------------------------------------------------------
__global__ void __launch_bounds__(512)
prep_kernel(const float* __restrict__ x1, const float* __restrict__ x2) {
    extern __shared__ char dyn[];
    float* sp  = (float*)dyn;                    // 3*NP floats (48 KB)
    int* hist  = (int*)(dyn + 3 * NP * sizeof(float));
    int* cur   = hist + NB2;
    __shared__ int wsum[16];

    const int s = blockIdx.x;
    const int w = s >> 5, b = s & 31;
    const float* src = (w ? x2 : x1) + (size_t)b * NP * 3;
    const int tid = threadIdx.x;

    const float4* src4 = (const float4*)src;
    float4* sp4 = (float4*)sp;
    for (int i = tid; i < 3 * NP / 4; i += 512)
        sp4[i] = src4[i];
    for (int i = tid; i < NB2; i += 512) hist[i] = 0;
    __syncthreads();

    for (int i = tid; i < NP; i += 512) {
        int bn = bco(sp[3 * i]) * NBY + bco(sp[3 * i + 1]);
        atomicAdd(&hist[bn], 1);
    }
    __syncthreads();

    // exclusive scan of 4096 bins: 512 threads x 8 bins each
    const int per = NB2 / 512;
    const int base = tid * per;
    int lsum = 0;
    #pragma unroll
    for (int i = 0; i < per; i++) lsum += hist[base + i];

    int lane = tid & 31, wid = tid >> 5;
    int v = lsum;
    #pragma unroll
    for (int o = 1; o < 32; o <<= 1) {
        int n = __shfl_up_sync(0xffffffffu, v, o);
        if (lane >= o) v += n;
    }
    if (lane == 31) wsum[wid] = v;
    __syncthreads();
    if (wid == 0) {
        int t = (lane < 16) ? wsum[lane] : 0;
        #pragma unroll
        for (int o = 1; o < 16; o <<= 1) {
            int n = __shfl_up_sync(0xffffffffu, t, o);
            if (lane >= o) t += n;
        }
        if (lane < 16) wsum[lane] = t;
    }
    __syncthreads();
    int run = (v - lsum) + (wid > 0 ? wsum[wid - 1] : 0);

    #pragma unroll
    for (int i = 0; i < per; i++) {
        int c = hist[base + i];
        g_bs[s][base + i] = run;
        cur[base + i] = run;
        run += c;
    }
    if (tid == 0) g_bs[s][NB2] = NP;
    __syncthreads();

    for (int i = tid; i < NP; i += 512) {
        float x = sp[3 * i], y = sp[3 * i + 1], z = sp[3 * i + 2];
        int bn = bco(x) * NBY + bco(y);
        int pos = atomicAdd(&cur[bn], 1);
        g_pts[s][pos] = make_float4(-2.0f * x, -2.0f * y, -2.0f * z,
                                    x * x + y * y + z * z);
        g_qid[s][pos] = (unsigned short)i;
    }
}

// scan [S,E) of SMEM-staged candidates with 4 accumulators
#define SCAN_SM(S, E)                                                           \
    {                                                                           \
        int _i = (S), _e = (E);                                                 \
        for (; _i + 4 <= _e; _i += 4) {                                         \
            float4 c0 = scand[_i],     c1 = scand[_i + 1];                      \
            float4 c2 = scand[_i + 2], c3 = scand[_i + 3];                      \
            m0 = fminf(m0, fmaf(qx, c0.x, fmaf(qy, c0.y, fmaf(qz, c0.z, c0.w)))); \
            m1 = fminf(m1, fmaf(qx, c1.x, fmaf(qy, c1.y, fmaf(qz, c1.z, c1.w)))); \
            m2 = fminf(m2, fmaf(qx, c2.x, fmaf(qy, c2.y, fmaf(qz, c2.z, c2.w)))); \
            m3 = fminf(m3, fmaf(qx, c3.x, fmaf(qy, c3.y, fmaf(qz, c3.z, c3.w)))); \
        }                                                                       \
        for (; _i < _e; _i++) {                                                 \
            float4 c0 = scand[_i];                                              \
            m0 = fminf(m0, fmaf(qx, c0.x, fmaf(qy, c0.y, fmaf(qz, c0.z, c0.w)))); \
        }                                                                       \
    }

// ---------------------------------------------------------------------------
// 2) query kernel: cloud in 64 KB SMEM. Pass A: warp-uniform (x,y)-rect
//    (each x-column one contiguous run). Fallback: radius-derived rect.
// ---------------------------------------------------------------------------
__global__ void __launch_bounds__(256)
query_kernel() {
    extern __shared__ float4 scand[];            // NP float4 = 64 KB

    const unsigned FULL = 0xffffffffu;
    const int sq = blockIdx.y;
    const int sc = sq ^ 32;                      // opposite cloud, same batch
    const int tid = threadIdx.x;
    const int qi = blockIdx.x * 256 + tid;       // bin-sorted query rank

    const float4* __restrict__ ptsq = g_pts[sq];
    const float4* __restrict__ ptsc = g_pts[sc];
    const int*    __restrict__ bs   = g_bs[sc];

    for (int j = tid; j < NP; j += 256)          // coalesced stage
        scand[j] = ptsc[j];
    __syncthreads();

    float4 qp = ptsq[qi];
    const int qid = g_qid[sq][qi];
    const float qx = -0.5f * qp.x;               // exact inverse of -2x
    const float qy = -0.5f * qp.y;
    const float qz = -0.5f * qp.z;
    const float qq = qp.w;

    const int bx = bco(qx);
    const int by = bco(qy);
    const int XL = max(__reduce_min_sync(FULL, bx) - 1, 0);
    const int XH = min(__reduce_max_sync(FULL, bx) + 1, NBX - 1);
    const int YL = max(__reduce_min_sync(FULL, by) - 1, 0);
    const int YH = min(__reduce_max_sync(FULL, by) + 1, NBY - 1);

    const float INF = __int_as_float(0x7f800000);
    float m0 = INF, m1 = INF, m2 = INF, m3 = INF;

    for (int x = XL; x <= XH; x++)               // one contiguous run per col
        SCAN_SM(bs[x * NBY + YL], bs[x * NBY + YH + 1]);

    float m = fminf(fminf(m0, m1), fminf(m2, m3));
    float ex0 = (XL == 0)       ? INF : qx - (XMIN + (float)XL * W);
    float ex1 = (XH == NBX - 1) ? INF : (XMIN + (float)(XH + 1) * W) - qx;
    float ey0 = (YL == 0)       ? INF : qy - (XMIN + (float)YL * W);
    float ey1 = (YH == NBY - 1) ? INF : (XMIN + (float)(YH + 1) * W) - qy;
    float bnd = fminf(fminf(ex0, ex1), fminf(ey0, ey1));
    float best = qq + m;
    bool fail = !(best <= bnd * bnd * 0.9999f);

    if (__any_sync(FULL, fail)) {
        float d = fail ? sqrtf(best * 1.0002f + 1e-6f) : 0.0f;
        int fxl = fail ? bco(qx - d) : NBX - 1;  // neutral sentinels
        int fxh = fail ? bco(qx + d) : 0;
        int fyl = fail ? bco(qy - d) : NBY - 1;
        int fyh = fail ? bco(qy + d) : 0;
        const int FXL = min(__reduce_min_sync(FULL, fxl), XL);
        const int FXH = max(__reduce_max_sync(FULL, fxh), XH);
        const int FYL = min(__reduce_min_sync(FULL, fyl), YL);
        const int FYH = max(__reduce_max_sync(FULL, fyh), YH);
        // scan fallback rect minus the already-scanned inner rect
        for (int x = FXL; x <= FXH; x++) {
            if (x >= XL && x <= XH) {            // overlap cols: only y-fringe
                if (FYL < YL) SCAN_SM(bs[x * NBY + FYL], bs[x * NBY + YL]);
                if (FYH > YH) SCAN_SM(bs[x * NBY + YH + 1], bs[x * NBY + FYH + 1]);
            } else {
                SCAN_SM(bs[x * NBY + FYL], bs[x * NBY + FYH + 1]);
            }
        }
        m = fminf(fminf(m0, m1), fminf(m2, m3));
        best = qq + m;
    }

    g_dist[sq][qid] = best;
}

// ---------------------------------------------------------------------------
// 3) deterministic fixed-order reduce: out[b] = (sum_d0 + sum_d1) / NP
// ---------------------------------------------------------------------------
__global__ void __launch_bounds__(256)
reduce_kernel(float* __restrict__ out) {
    const int b = blockIdx.x, tid = threadIdx.x;
    float s = 0.0f;
    #pragma unroll
    for (int d = 0; d < 2; d++)
        for (int i = tid; i < NP; i += 256)
            s += g_dist[d * BATCH + b][i];

    __shared__ float red[256];
    red[tid] = s;
    __syncthreads();
    #pragma unroll
    for (int o = 128; o > 0; o >>= 1) {
        if (tid < o) red[tid] += red[tid + o];
        __syncthreads();
    }
    if (tid == 0) out[b] = red[0] * (1.0f / (float)NP);
}

extern "C" void kernel_launch(void* const* d_in, const int* in_sizes, int n_in,
                              void* d_out, int out_size) {
    const float* x1 = (const float*)d_in[0];
    const float* x2 = (const float*)d_in[1];
    float* out = (float*)d_out;

    const int prep_smem = 3 * NP * (int)sizeof(float) + 2 * NB2 * (int)sizeof(int);
    cudaFuncSetAttribute(prep_kernel,
                         cudaFuncAttributeMaxDynamicSharedMemorySize, prep_smem);
    cudaFuncSetAttribute(query_kernel,
                         cudaFuncAttributeMaxDynamicSharedMemorySize,
                         NP * (int)sizeof(float4));

    prep_kernel<<<NSLOT, 512, prep_smem>>>(x1, x2);
    query_kernel<<<dim3(NP / 256, NSLOT), 256, NP * sizeof(float4)>>>();
    reduce_kernel<<<BATCH, 256>>>(out);
}